// round 1
// baseline (speedup 1.0000x reference)
#include <cuda_runtime.h>
#include <math.h>

#define HW 1024
#define CC 1024
#define CR 64

// ---------------- scratch (__device__ globals: no allocation allowed) ----------------
__device__ float g_A[32 * 32];        // row-normalized 1D gaussian, A[i*32+x]
__device__ float g_mean[CC];          // per-channel spatial mean
__device__ float g_scale[CC];         // SE sigmoid scale
__device__ float g_xr[CC * HW];       // sigmoid(x_se)
__device__ float g_cat[2 * CC * HW];  // [0..1023]=x_range, [1024..2047]=x_spatial

// ---------------- 1D gaussian table (separable form of the reference's gus) --------
__global__ void k_init_A() {
    int t = threadIdx.x;          // 1024 threads: warp i handles row i
    int i = t >> 5, x = t & 31;
    float d = (float)(i - x);
    float e = expf(-d * d / 4.5f);   // 2*sigma^2 = 4.5
    float s = e;
    #pragma unroll
    for (int o = 16; o > 0; o >>= 1) s += __shfl_xor_sync(0xffffffffu, s, o);
    g_A[i * 32 + x] = e / s;      // 1/(2*pi*sigma^2) cancels in normalization
}

// ---------------- per-channel spatial mean ----------------
__global__ void k_mean(const float* __restrict__ x) {
    int c = blockIdx.x;
    const float* xc = x + c * HW;
    float s = 0.f;
    for (int i = threadIdx.x; i < HW; i += 256) s += xc[i];
    #pragma unroll
    for (int o = 16; o > 0; o >>= 1) s += __shfl_xor_sync(0xffffffffu, s, o);
    __shared__ float red[8];
    int lane = threadIdx.x & 31, w = threadIdx.x >> 5;
    if (lane == 0) red[w] = s;
    __syncthreads();
    if (threadIdx.x == 0) {
        float t = 0.f;
        #pragma unroll
        for (int i = 0; i < 8; i++) t += red[i];
        g_mean[c] = t * (1.0f / 1024.0f);
    }
}

// ---------------- SE MLP: relu(W1 y + b1) -> sigmoid(W2 h + b2) ----------------
__global__ void k_se(const float* __restrict__ w1, const float* __restrict__ b1,
                     const float* __restrict__ w2, const float* __restrict__ b2) {
    __shared__ float ym[CC];
    __shared__ float h1[CR];
    int t = threadIdx.x;  // 256
    for (int i = t; i < CC; i += 256) ym[i] = g_mean[i];
    __syncthreads();
    {
        // 4 threads per output row j
        int j = t >> 2, l4 = t & 3;
        const float* wr = w1 + j * CC;
        float s = 0.f;
        for (int k = l4; k < CC; k += 4) s += wr[k] * ym[k];
        s += __shfl_xor_sync(0xffffffffu, s, 1);
        s += __shfl_xor_sync(0xffffffffu, s, 2);
        if (l4 == 0) h1[j] = fmaxf(s + b1[j], 0.f);
    }
    __syncthreads();
    for (int c = t; c < CC; c += 256) {
        const float* wr = w2 + c * CR;
        float s = b2[c];
        #pragma unroll
        for (int k = 0; k < CR; k++) s += wr[k] * h1[k];
        g_scale[c] = 1.f / (1.f + expf(-s));
    }
}

// ---------------- per channel: scale, sigmoid (xr), separable gaussian (x_spatial) --
__global__ void k_channel(const float* __restrict__ x) {
    __shared__ float xs[32][33];
    __shared__ float Acol[32][33];  // Acol[y][k] = A[k][y]
    __shared__ float tm[32][33];
    int c = blockIdx.x;
    int t = threadIdx.x;            // 1024 threads
    int r = t >> 5, kk = t & 31;
    float sc = g_scale[c];
    float v = x[c * HW + t] * sc;
    xs[r][kk] = v;                  // xs[h][w]
    g_xr[c * HW + t] = 1.f / (1.f + expf(-v));
    Acol[kk][r] = g_A[t];           // t = k*32+y -> Acol[y][k]
    __syncthreads();
    // tmp[x][k] = sum_y xs[x][y] * A[k][y]
    float s = 0.f;
    #pragma unroll
    for (int y = 0; y < 32; y++) s += xs[r][y] * Acol[y][kk];
    tm[r][kk] = s;
    __syncthreads();
    // out[i][k] = sum_x A[i][x] * tmp[x][k]
    float s2 = 0.f;
    #pragma unroll
    for (int xx = 0; xx < 32; xx++) s2 += Acol[xx][r] * tm[xx][kk];
    g_cat[(CC + c) * HW + r * 32 + kk] = s2;
}

// ---------------- scrambled 3x3 softmax attention (faithful to reference reshape) ---
__global__ void k_attn() {
    __shared__ float sv[9 * 1024];
    __shared__ float lg[9];
    __shared__ float attn[9];
    int p = blockIdx.x;
    int py = p >> 5, px = p & 31;
    int t = threadIdx.x;  // 256
    if (t < 9) lg[t] = 0.f;
    __syncthreads();
    float pl[9];
    #pragma unroll
    for (int j = 0; j < 9; j++) pl[j] = 0.f;

    #pragma unroll
    for (int q = 0; q < 4; q++) {
        int cc = t + q * 256;
        float x1v = g_xr[cc * HW + p];
        #pragma unroll
        for (int j = 0; j < 9; j++) {
            int F = j * 1024 + cc;
            int c2 = F / 9;
            int kidx = F - c2 * 9;
            int sy = py + kidx / 3 - 1;
            int sx = px + kidx - (kidx / 3) * 3 - 1;
            float v = 0.f;
            if ((unsigned)sy < 32u && (unsigned)sx < 32u)
                v = g_xr[c2 * HW + sy * 32 + sx];
            sv[j * 1024 + cc] = v;
            pl[j] += x1v * v;
        }
    }
    #pragma unroll
    for (int j = 0; j < 9; j++) {
        float s = pl[j];
        #pragma unroll
        for (int o = 16; o > 0; o >>= 1) s += __shfl_xor_sync(0xffffffffu, s, o);
        if ((t & 31) == 0) atomicAdd(&lg[j], s);
    }
    __syncthreads();
    if (t == 0) {
        float m = lg[0];
        #pragma unroll
        for (int j = 1; j < 9; j++) m = fmaxf(m, lg[j]);
        float e[9], ss = 0.f;
        #pragma unroll
        for (int j = 0; j < 9; j++) { e[j] = expf(lg[j] - m); ss += e[j]; }
        float inv = 1.f / ss;
        #pragma unroll
        for (int j = 0; j < 9; j++) attn[j] = e[j] * inv;
    }
    __syncthreads();
    #pragma unroll
    for (int q = 0; q < 4; q++) {
        int cc = t + q * 256;
        float acc = 0.f;
        #pragma unroll
        for (int j = 0; j < 9; j++) acc += attn[j] * sv[j * 1024 + cc];
        g_cat[cc * HW + p] = acc;
    }
}

// ---------------- fused 1x1 conv (GEMM 1024x1024x2048) + BN + ReLU ----------------
// BM=128, BN=64, BK=16, 256 threads, TM=8, TN=4. grid = (16, 8)
__global__ void k_gemm(const float* __restrict__ Wc,
                       const float* __restrict__ gamma, const float* __restrict__ beta,
                       const float* __restrict__ mean, const float* __restrict__ var,
                       float* __restrict__ out) {
    __shared__ float As[16][128];
    __shared__ float Bs[16][64];
    int tid = threadIdx.x;
    int tx = tid & 15, ty = tid >> 4;
    int pcol0 = blockIdx.x * 64;
    int orow0 = blockIdx.y * 128;
    float acc[8][4];
    #pragma unroll
    for (int i = 0; i < 8; i++)
        #pragma unroll
        for (int j = 0; j < 4; j++) acc[i][j] = 0.f;

    for (int kt = 0; kt < 2048; kt += 16) {
        #pragma unroll
        for (int l = 0; l < 2; l++) {
            int q = tid + l * 256;
            int ar = q >> 2;
            int ac = (q & 3) * 4;
            float4 v = *(const float4*)(Wc + (orow0 + ar) * 2048 + kt + ac);
            As[ac + 0][ar] = v.x; As[ac + 1][ar] = v.y;
            As[ac + 2][ar] = v.z; As[ac + 3][ar] = v.w;
        }
        {
            int br = tid >> 4;
            int bc = (tid & 15) * 4;
            float4 v = *(const float4*)(g_cat + (kt + br) * 1024 + pcol0 + bc);
            *(float4*)&Bs[br][bc] = v;
        }
        __syncthreads();
        #pragma unroll
        for (int k = 0; k < 16; k++) {
            float a[8], b[4];
            #pragma unroll
            for (int i = 0; i < 8; i++) a[i] = As[k][ty * 8 + i];
            #pragma unroll
            for (int j = 0; j < 4; j++) b[j] = Bs[k][tx * 4 + j];
            #pragma unroll
            for (int i = 0; i < 8; i++)
                #pragma unroll
                for (int j = 0; j < 4; j++) acc[i][j] += a[i] * b[j];
        }
        __syncthreads();
    }
    #pragma unroll
    for (int i = 0; i < 8; i++) {
        int o = orow0 + ty * 8 + i;
        float invg = rsqrtf(var[o] + 1e-5f) * gamma[o];
        float mb = mean[o], bb = beta[o];
        #pragma unroll
        for (int j = 0; j < 4; j++) {
            float vv = (acc[i][j] - mb) * invg + bb;
            out[o * 1024 + pcol0 + tx * 4 + j] = fmaxf(vv, 0.f);
        }
    }
}

extern "C" void kernel_launch(void* const* d_in, const int* in_sizes, int n_in,
                              void* d_out, int out_size) {
    const float* x     = (const float*)d_in[0];
    const float* w1    = (const float*)d_in[1];
    const float* b1    = (const float*)d_in[2];
    const float* w2    = (const float*)d_in[3];
    const float* b2    = (const float*)d_in[4];
    const float* cw    = (const float*)d_in[5];
    const float* gamma = (const float*)d_in[6];
    const float* beta  = (const float*)d_in[7];
    const float* mean  = (const float*)d_in[8];
    const float* var   = (const float*)d_in[9];
    float* out = (float*)d_out;

    k_init_A<<<1, 1024>>>();
    k_mean<<<1024, 256>>>(x);
    k_se<<<1, 256>>>(w1, b1, w2, b2);
    k_channel<<<1024, 1024>>>(x);
    k_attn<<<1024, 256>>>();
    dim3 g(16, 8);
    k_gemm<<<g, 256>>>(cw, gamma, beta, mean, var, out);
}